// round 15
// baseline (speedup 1.0000x reference)
#include <cuda_runtime.h>
#include <cstdint>

// Transformer_66529043415377 — warp-autonomous async-bulk zero stores, v5.
//
// Reference quirks: y clamped to [0, C-1]=[0,2], x to [0, H-1]=[0,511],
// raw [N,3] channel-interleaved output.
//
// Exact-zero structure (bit-exact since R2): with the reference's rounding
// order a pixel is nonzero ONLY when y = h + 64*dy lies in [0,2). Otherwise
// both clamped rows coincide, wb=-wa, wd=-wc exactly, and the left-assoc
// sum cancels to +0.0.
//
// R15 design: NO block barriers. Each warp owns a private 1536B SMEM zero
// region (filled once, __syncwarp only) and processes T=2 tiles of 128 px:
// both dy LDG.128s front-batched (MLP=2), per-tile __ballot_sync activity
// test, lane0 issues a 1536B cp.async.bulk zero store per tile. Patch path
// (rare): lane0 wait_group 0, __syncwarp, bit-exact bilinear overwrite.
// No exit wait: every warp writes the same zeros at the same SMEM offsets,
// so SMEM reuse by a successor CTA is a value-free race (proved in R14).

namespace {
constexpr int B  = 16;
constexpr int H  = 512;
constexpr int W  = 512;
constexpr int HW = H * W;            // 262144
constexpr int N  = B * HW;           // 4194304 pixels
constexpr int THREADS = 128;
constexpr int WARPS_PER_CTA = 4;
constexpr int TILE_PX    = 128;                  // per-warp tile
constexpr int TILE_BYTES = TILE_PX * 3 * 4;      // 1536
constexpr int T = 2;                             // tiles per warp
constexpr int TOT_WARPS = N / (TILE_PX * T);     // 16384
constexpr int CTAS = TOT_WARPS / WARPS_PER_CTA;  // 4096
constexpr int ZF4_PER_WARP = TILE_BYTES / 16;    // 96 float4
}

__device__ __forceinline__ uint32_t smem_u32(const void* p) {
    uint32_t a;
    asm("{ .reg .u64 t; cvta.to.shared.u64 t, %1; cvt.u32.u64 %0, t; }"
        : "=r"(a) : "l"(p));
    return a;
}

__global__ __launch_bounds__(THREADS)
void transformer_warp_kernel(const float* __restrict__ flow,
                             const float* __restrict__ pqf,
                             float* __restrict__ out)
{
    __shared__ float4 zbuf[WARPS_PER_CTA * ZF4_PER_WARP];   // 6 KB

    const int tid = threadIdx.x;
    const int wid = tid >> 5;
    const int lid = tid & 31;

    // One-time per-warp zero fill of its private 1536B region (3 STS.128).
    float4* zb = zbuf + wid * ZF4_PER_WARP;
    const float4 z = make_float4(0.0f, 0.0f, 0.0f, 0.0f);
    zb[lid]      = z;
    zb[lid + 32] = z;
    zb[lid + 64] = z;
    __syncwarp();
    const uint32_t saddr = smem_u32(zb);
    if (lid == 0)
        asm volatile("fence.proxy.async.shared::cta;" ::: "memory");

    const int wg    = blockIdx.x * WARPS_PER_CTA + wid;  // global warp id
    const int tile0 = wg * T;
    const int i0    = tile0 * TILE_PX;          // warp covers 256 px, batch-aligned
    const int b     = i0 >> 18;                 // constant across both tiles
    const int baseb = b << 9;                   // b * dim1 (=W=512)
    const float* fb0 = flow + (size_t)b * 2 * HW;

    // Front-batched dy loads for both tiles (per-warp MLP=2).
    const int rem0 = (i0 + lid * 4) & (HW - 1);
    const int rem1 = (i0 + TILE_PX + lid * 4) & (HW - 1);
    const float4 dyA = *reinterpret_cast<const float4*>(fb0 + HW + rem0);
    const float4 dyB = *reinterpret_cast<const float4*>(fb0 + HW + rem1);

    const int   rems[2] = {rem0, rem1};
    const float4 dys[2] = {dyA, dyB};

#pragma unroll
    for (int tt = 0; tt < T; ++tt) {
        const int remk = rems[tt];
        const int h = remk >> 9;
        const int w = remk & (W - 1);
        const float4 dy4 = dys[tt];

        const float yf = (float)h;
        // fmaf bit-exact: dy*64 exact (power-of-two scale)
        const float y0 = __fmaf_rn(dy4.x, 64.0f, yf);
        const float y1 = __fmaf_rn(dy4.y, 64.0f, yf);
        const float y2 = __fmaf_rn(dy4.z, 64.0f, yf);
        const float y3 = __fmaf_rn(dy4.w, 64.0f, yf);

        const bool a0 = (y0 >= 0.0f) && (y0 < 2.0f);
        const bool a1 = (y1 >= 0.0f) && (y1 < 2.0f);
        const bool a2 = (y2 >= 0.0f) && (y2 < 2.0f);
        const bool a3 = (y3 >= 0.0f) && (y3 < 2.0f);
        const bool any = a0 | a1 | a2 | a3;

        const unsigned ball = __ballot_sync(0xFFFFFFFFu, any);

        // Lane 0 issues the 1536B bulk zero store for this warp-tile.
        if (lid == 0) {
            const float* gdst = out + (size_t)(tile0 + tt) * TILE_PX * 3;
            asm volatile(
                "cp.async.bulk.global.shared::cta.bulk_group [%0], [%1], %2;"
                :: "l"(gdst), "r"(saddr), "r"(TILE_BYTES) : "memory");
            asm volatile("cp.async.bulk.commit_group;" ::: "memory");
        }

        if (ball == 0) continue;                // whole tile is exact zeros

        // Patch ordering: zeros must land before patch STGs (same lines).
        if (lid == 0)
            asm volatile("cp.async.bulk.wait_group 0;" ::: "memory");
        __syncwarp();
        if (!any) continue;

        const float4 dx4 = *reinterpret_cast<const float4*>(fb0 + remk);
        const float dxs[4] = {dx4.x, dx4.y, dx4.z, dx4.w};
        const float yv[4]  = {y0, y1, y2, y3};
        const bool  act[4] = {a0, a1, a2, a3};
        const int   i      = (tile0 + tt) * TILE_PX + lid * 4;

#pragma unroll
        for (int j = 0; j < 4; ++j) {
            if (!act[j]) continue;

            const float y = yv[j];
            const float x = __fmaf_rn(dxs[j], 64.0f, (float)(w + j)); // exact

            float x0f = floorf(x);
            float x1f = __fadd_rn(x0f, 1.0f);
            x0f = fminf(fmaxf(x0f, 0.0f), 511.0f);  // max_x = H-1 = 511
            x1f = fminf(fmaxf(x1f, 0.0f), 511.0f);

            // active => y in [0,2): clamps no-ops; equals reference's y0,y1
            const float y0f = floorf(y);
            const float y1f = __fadd_rn(y0f, 1.0f);

            const int ix0 = (int)x0f;
            const int ix1 = (int)x1f;
            const int iy0 = (int)y0f;
            const int iy1 = (int)y1f;

            const int idx_a = baseb + iy0 * HW + ix0;
            const int idx_b = baseb + iy1 * HW + ix0;
            const int idx_c = baseb + iy0 * HW + ix1;
            const int idx_d = baseb + iy1 * HW + ix1;

            // single-rounded weight products (no contractible fma pattern)
            const float wxa = __fsub_rn(x1f, x);
            const float wxc = __fsub_rn(x, x0f);
            const float wya = __fsub_rn(y1f, y);
            const float wyb = __fsub_rn(y, y0f);
            const float wa = __fmul_rn(wxa, wya);
            const float wb = __fmul_rn(wxa, wyb);
            const float wc = __fmul_rn(wxc, wya);
            const float wd = __fmul_rn(wxc, wyb);

            const float* pa = pqf + (size_t)idx_a * 3;
            const float* pb = pqf + (size_t)idx_b * 3;
            const float* pc = pqf + (size_t)idx_c * 3;
            const float* pd = pqf + (size_t)idx_d * 3;

            float* op = out + (size_t)(i + j) * 3;
#pragma unroll
            for (int c = 0; c < 3; ++c) {
                // exact reference order: ((wa*A + wb*B) + wc*C) + wd*D,
                // each product individually rounded, no contraction
                const float pA = __fmul_rn(wa, __ldg(pa + c));
                const float pB = __fmul_rn(wb, __ldg(pb + c));
                const float pC = __fmul_rn(wc, __ldg(pc + c));
                const float pD = __fmul_rn(wd, __ldg(pd + c));
                op[c] = __fadd_rn(__fadd_rn(__fadd_rn(pA, pB), pC), pD);
            }
        }
    }
    // No exit wait: SMEM reuse by a successor CTA is a value-free race
    // (identical zero bytes at identical offsets) — validated in R14.
}

extern "C" void kernel_launch(void* const* d_in, const int* in_sizes, int n_in,
                              void* d_out, int out_size)
{
    const float* flow = (const float*)d_in[0];
    const float* pqf  = (const float*)d_in[1];
    float* out        = (float*)d_out;

    transformer_warp_kernel<<<CTAS, THREADS>>>(flow, pqf, out);
}

// round 16
// speedup vs baseline: 1.1060x; 1.1060x over previous
#include <cuda_runtime.h>
#include <cstdint>

// Transformer_66529043415377 — fused kernel, async-bulk zero stores, v6.
//
// Reference quirks: y clamped to [0, C-1]=[0,2], x to [0, H-1]=[0,511],
// raw [N,3] channel-interleaved output.
//
// Exact-zero structure (bit-exact since R2): with the reference's rounding
// order a pixel is nonzero ONLY when y = h + 64*dy lies in [0,2). Otherwise
// both clamped rows coincide, wb=-wa, wd=-wc exactly, and the left-assoc
// sum cancels to +0.0.
//
// R16 change vs R14 (13.2 us): SINGLE block barrier. __syncthreads_or has
// full __syncthreads memory semantics, so issuing the bulk store AFTER the
// vote lets the vote barrier double as the STS-before-bulk ordering point.
// Fast path: dy LDG + 3xSTS -> compute -> syncthreads_or -> tid0 bulk -> exit.
// No exit wait (R14: SMEM reuse by a successor CTA is a value-free race —
// identical zero bytes at identical offsets). Patch path keeps
// wait_group 0 + __syncthreads (zeros must land before patch STGs).

namespace {
constexpr int B  = 16;
constexpr int H  = 512;
constexpr int W  = 512;
constexpr int HW = H * W;            // 262144
constexpr int N  = B * HW;           // 4194304 pixels
constexpr int PIX = 4;
constexpr int THREADS = 128;
constexpr int PX_PER_CTA = PIX * THREADS;         // 512
constexpr int BYTES_PER_CTA = PX_PER_CTA * 3 * 4; // 6144
}

__device__ __forceinline__ uint32_t smem_u32(const void* p) {
    uint32_t a;
    asm("{ .reg .u64 t; cvta.to.shared.u64 t, %1; cvt.u32.u64 %0, t; }"
        : "=r"(a) : "l"(p));
    return a;
}

__global__ __launch_bounds__(THREADS)
void transformer_warp_kernel(const float* __restrict__ flow,
                             const float* __restrict__ pqf,
                             float* __restrict__ out)
{
    __shared__ float4 zbuf[BYTES_PER_CTA / 16];  // 6 KB of zeros

    const int tid = threadIdx.x;

    const int t = blockIdx.x * THREADS + tid;
    const int i = t * PIX;                      // base pixel index

    const int b   = i >> 18;                    // / HW
    const int rem = i & (HW - 1);
    const int h   = rem >> 9;                   // / W
    const int w   = rem & (W - 1);

    // dy load first — flies while the STS fill issues.
    const float* fbase = flow + (size_t)b * 2 * HW + rem;
    const float4 dy4 = *reinterpret_cast<const float4*>(fbase + HW);

    // Zero the SMEM tile (3 STS.128 per thread).
    const float4 z = make_float4(0.0f, 0.0f, 0.0f, 0.0f);
    zbuf[tid]       = z;
    zbuf[tid + 128] = z;
    zbuf[tid + 256] = z;

    const float yf = (float)h;

    // fmaf bit-exact: dy*64 exact (power-of-two scale)
    const float y0 = __fmaf_rn(dy4.x, 64.0f, yf);
    const float y1 = __fmaf_rn(dy4.y, 64.0f, yf);
    const float y2 = __fmaf_rn(dy4.z, 64.0f, yf);
    const float y3 = __fmaf_rn(dy4.w, 64.0f, yf);

    const bool a0 = (y0 >= 0.0f) && (y0 < 2.0f);
    const bool a1 = (y1 >= 0.0f) && (y1 < 2.0f);
    const bool a2 = (y2 >= 0.0f) && (y2 < 2.0f);
    const bool a3 = (y3 >= 0.0f) && (y3 < 2.0f);
    const bool any = a0 | a1 | a2 | a3;

    // ONE barrier: activity vote + orders all STS before the bulk read.
    const int cta_any = __syncthreads_or((int)any);

    // Bulk zero store of the CTA's 6 KB output span (async proxy, no L1).
    if (tid == 0) {
        asm volatile("fence.proxy.async.shared::cta;" ::: "memory");
        const uint32_t saddr = smem_u32(zbuf);
        const float*   gdst  = out + (size_t)blockIdx.x * (BYTES_PER_CTA / 4);
        asm volatile(
            "cp.async.bulk.global.shared::cta.bulk_group [%0], [%1], %2;"
            :: "l"(gdst), "r"(saddr), "r"(BYTES_PER_CTA) : "memory");
        asm volatile("cp.async.bulk.commit_group;" ::: "memory");
    }

    // Fast path: no exit wait (value-free SMEM reuse race, proven R14).
    if (cta_any == 0) return;

    // Patch ordering: zeros must fully land before patch STGs.
    if (tid == 0)
        asm volatile("cp.async.bulk.wait_group 0;" ::: "memory");
    __syncthreads();
    if (!any) return;

    // Rare path: patch active pixels over the zeros (bit-exact ref order).
    const float4 dx4 = *reinterpret_cast<const float4*>(fbase);
    const float dxs[4] = {dx4.x, dx4.y, dx4.z, dx4.w};
    const float yv[4]  = {y0, y1, y2, y3};
    const bool  act[4] = {a0, a1, a2, a3};

    const int baseb = b << 9;                   // b * dim1 (=W=512)

#pragma unroll
    for (int j = 0; j < 4; ++j) {
        if (!act[j]) continue;

        const float y = yv[j];
        const float x = __fmaf_rn(dxs[j], 64.0f, (float)(w + j)); // bit-exact

        float x0f = floorf(x);
        float x1f = __fadd_rn(x0f, 1.0f);
        x0f = fminf(fmaxf(x0f, 0.0f), 511.0f);  // max_x = H-1 = 511
        x1f = fminf(fmaxf(x1f, 0.0f), 511.0f);

        // active => y in [0,2): clamps no-ops; equals reference's y0,y1
        const float y0f = floorf(y);
        const float y1f = __fadd_rn(y0f, 1.0f);

        const int ix0 = (int)x0f;
        const int ix1 = (int)x1f;
        const int iy0 = (int)y0f;
        const int iy1 = (int)y1f;

        const int idx_a = baseb + iy0 * HW + ix0;
        const int idx_b = baseb + iy1 * HW + ix0;
        const int idx_c = baseb + iy0 * HW + ix1;
        const int idx_d = baseb + iy1 * HW + ix1;

        // single-rounded weight products (no contractible fma pattern)
        const float wxa = __fsub_rn(x1f, x);
        const float wxc = __fsub_rn(x, x0f);
        const float wya = __fsub_rn(y1f, y);
        const float wyb = __fsub_rn(y, y0f);
        const float wa = __fmul_rn(wxa, wya);
        const float wb = __fmul_rn(wxa, wyb);
        const float wc = __fmul_rn(wxc, wya);
        const float wd = __fmul_rn(wxc, wyb);

        const float* pa = pqf + (size_t)idx_a * 3;
        const float* pb = pqf + (size_t)idx_b * 3;
        const float* pc = pqf + (size_t)idx_c * 3;
        const float* pd = pqf + (size_t)idx_d * 3;

        float* op = out + (size_t)(i + j) * 3;
#pragma unroll
        for (int c = 0; c < 3; ++c) {
            // exact reference order: ((wa*A + wb*B) + wc*C) + wd*D,
            // each product individually rounded, no contraction
            const float pA = __fmul_rn(wa, __ldg(pa + c));
            const float pB = __fmul_rn(wb, __ldg(pb + c));
            const float pC = __fmul_rn(wc, __ldg(pc + c));
            const float pD = __fmul_rn(wd, __ldg(pd + c));
            op[c] = __fadd_rn(__fadd_rn(__fadd_rn(pA, pB), pC), pD);
        }
    }
}

extern "C" void kernel_launch(void* const* d_in, const int* in_sizes, int n_in,
                              void* d_out, int out_size)
{
    const float* flow = (const float*)d_in[0];
    const float* pqf  = (const float*)d_in[1];
    float* out        = (float*)d_out;

    const int blocks = N / PX_PER_CTA;          // 8192
    transformer_warp_kernel<<<blocks, THREADS>>>(flow, pqf, out);
}